// round 9
// baseline (speedup 1.0000x reference)
#include <cuda_runtime.h>
#include <cuda_bf16.h>
#include <stdint.h>

#define NN 50000
#define EE 600000
#define Hh 128
#define EDdim 16
#define Bb 256
#define Ll 5
#define NBLK 196                    // ceil(NN/256)
#define GBLK2 ((NN + 63) / 64)      // 782 GEMM CTAs (64 rows each)
#define STRIDE 136                  // padded bf16 row stride in smem
#define BLO_ELEM (128 * STRIDE)     // lo-plane offset in bf16 elems
#define GEMM_SMEM (2 * 128 * STRIDE * 2)   // B hi+lo only: 69,632 bytes

// ======================= device scratch =======================
__device__ float g_x[(size_t)NN * Hh];
__device__ float g_h[(size_t)NN * Hh];
__device__ float g_agg[(size_t)NN * Hh];
__device__ float g_eagg[(size_t)NN * EDdim];
__device__ int   g_deg[NN];
__device__ int   g_rowptr[NN + 1];
__device__ int   g_cursor[NN];
__device__ int   g_srcA[EE];
__device__ int   g_eidA[EE];
__device__ int   g_bsum[NBLK];
__device__ int   g_boff[NBLK];
__device__ float g_counts[Bb];
__device__ float g_pooled[Bb * Hh];
__device__ float g_vn[Bb * Hh];
__device__ __nv_bfloat16 g_whi[15 * Hh * Hh];  // [mat][n][k] transposed split
__device__ __nv_bfloat16 g_wlo[15 * Hh * Hh];

// ======================= preprocessing =======================
__global__ void k_wsplit(const float* __restrict__ nodeW, const float* __restrict__ m1W,
                         const float* __restrict__ m2W) {
    int b = blockIdx.x;
    int mat = b >> 6;
    int idx = ((b & 63) << 8) + threadIdx.x;   // 0..16383 over [n][k]
    const float* Wsrc = (mat < 5) ? (nodeW + (size_t)mat * Hh * Hh)
                      : (mat < 10) ? (m1W + (size_t)(mat - 5) * Hh * Hh)
                      : (m2W + (size_t)(mat - 10) * Hh * Hh);
    int n = idx >> 7, k = idx & 127;
    float w = Wsrc[k * Hh + n];
    __nv_bfloat16 hi = __float2bfloat16(w);
    __nv_bfloat16 lo = __float2bfloat16(w - __bfloat162float(hi));
    g_whi[(size_t)mat * Hh * Hh + idx] = hi;
    g_wlo[(size_t)mat * Hh * Hh + idx] = lo;
}

__global__ void k_vn_init(const float* __restrict__ vninit) {
    g_vn[blockIdx.x * Hh + threadIdx.x] = vninit[threadIdx.x];
}

__global__ void k_counts(const int* __restrict__ batch) {
    int i = blockIdx.x * 256 + threadIdx.x;
    if (i < NN) atomicAdd(&g_counts[batch[i]], 1.0f);
}

__global__ void k_deg(const int* __restrict__ dst) {
    int e = blockIdx.x * 256 + threadIdx.x;
    if (e < EE) atomicAdd(&g_deg[dst[e]], 1);
}

__global__ void k_bsum() {
    __shared__ int s[256];
    int t = threadIdx.x;
    int i = blockIdx.x * 256 + t;
    s[t] = (i < NN) ? g_deg[i] : 0;
    __syncthreads();
    for (int o = 128; o > 0; o >>= 1) {
        if (t < o) s[t] += s[t + o];
        __syncthreads();
    }
    if (t == 0) g_bsum[blockIdx.x] = s[0];
}

__global__ void k_bscan() {
    __shared__ int s[256];
    int t = threadIdx.x;
    int v = (t < NBLK) ? g_bsum[t] : 0;
    s[t] = v;
    __syncthreads();
    for (int o = 1; o < 256; o <<= 1) {
        int u = (t >= o) ? s[t - o] : 0;
        __syncthreads();
        s[t] += u;
        __syncthreads();
    }
    if (t < NBLK) g_boff[t] = s[t] - v;
    if (t == 255) g_rowptr[NN] = s[255];
}

__global__ void k_bfill() {
    __shared__ int s[256];
    int t = threadIdx.x;
    int i = blockIdx.x * 256 + t;
    int v = (i < NN) ? g_deg[i] : 0;
    s[t] = v;
    __syncthreads();
    for (int o = 1; o < 256; o <<= 1) {
        int u = (t >= o) ? s[t - o] : 0;
        __syncthreads();
        s[t] += u;
        __syncthreads();
    }
    if (i < NN) {
        int pos = g_boff[blockIdx.x] + s[t] - v;
        g_rowptr[i] = pos;
        g_cursor[i] = pos;
    }
}

__global__ void k_fill(const int* __restrict__ src, const int* __restrict__ dst) {
    int e = blockIdx.x * 256 + threadIdx.x;
    if (e >= EE) return;
    int d = dst[e];
    int pos = atomicAdd(&g_cursor[d], 1);
    g_srcA[pos] = src[e];
    g_eidA[pos] = e;
}

__global__ void k_eagg(const float* __restrict__ eattr) {
    int w = (blockIdx.x * 256 + threadIdx.x) >> 5;
    int lane = threadIdx.x & 31;
    if (w >= NN || lane >= EDdim) return;
    int beg = g_rowptr[w], end = g_rowptr[w + 1];
    float s = 0.f;
    for (int e = beg; e < end; e++) {
        int eid = g_eidA[e];
        s += eattr[(size_t)eid * EDdim + lane];
    }
    g_eagg[w * EDdim + lane] = s;
}

// ======================= HMMA bf16-split GEMM v5 (32x32 warp tile, 3 CTAs/SM) ============
// C[M,128] = A[M,128] @ W[128,128]; D = Ahi@Bhi + Ahi@Blo + Alo@Bhi (fp32 accum).
// CTA: 64 rows x 128 cols, 8 warps (2 row-bands x 4 col-groups), warp tile 32x32.
// EPI 0: +bias +vn[batch]; EPI 1: relu(+bias); EPI 2: relu(+bias) + pooled atomic.

__device__ __forceinline__ void mma16816(float* c, uint32_t a0, uint32_t a1, uint32_t a2,
                                         uint32_t a3, uint32_t b0, uint32_t b1) {
    asm volatile(
        "mma.sync.aligned.m16n8k16.row.col.f32.bf16.bf16.f32 "
        "{%0,%1,%2,%3}, {%4,%5,%6,%7}, {%8,%9}, {%0,%1,%2,%3};"
        : "+f"(c[0]), "+f"(c[1]), "+f"(c[2]), "+f"(c[3])
        : "r"(a0), "r"(a1), "r"(a2), "r"(a3), "r"(b0), "r"(b1));
}

#define LDSM4(r0, r1, r2, r3, addr) \
    asm volatile("ldmatrix.sync.aligned.m8n8.x4.shared.b16 {%0,%1,%2,%3}, [%4];" \
                 : "=r"(r0), "=r"(r1), "=r"(r2), "=r"(r3) : "r"(addr))

__device__ __forceinline__ uint32_t smem_to_u32(const void* p) {
    uint32_t a;
    asm("{ .reg .u64 t; cvta.to.shared.u64 t, %1; cvt.u32.u64 %0, t; }" : "=r"(a) : "l"(p));
    return a;
}

// pack float2 (v.x = even k, v.y = odd k) into bf16x2 hi + residual lo words
__device__ __forceinline__ void packsplit(float2 v, uint32_t& h, uint32_t& l) {
    uint32_t hp;
    asm("cvt.rn.bf16x2.f32 %0, %1, %2;" : "=r"(hp) : "f"(v.y), "f"(v.x));
    float h0 = __uint_as_float(hp << 16);
    float h1 = __uint_as_float(hp & 0xffff0000u);
    uint32_t lp;
    asm("cvt.rn.bf16x2.f32 %0, %1, %2;" : "=r"(lp) : "f"(v.y - h1), "f"(v.x - h0));
    h = hp;
    l = lp;
}

template <int EPI>
__launch_bounds__(256, 3)
__global__ void gemm_tc(const float* __restrict__ A, const __nv_bfloat16* __restrict__ Whi,
                        const __nv_bfloat16* __restrict__ Wlo, const float* __restrict__ bias,
                        float* __restrict__ C, const int* __restrict__ batch,
                        const float* __restrict__ vn, float* __restrict__ pooled, int M) {
    extern __shared__ __nv_bfloat16 sm[];
    const int tid = threadIdx.x;
    const int wid = tid >> 5;
    const int lane = tid & 31;
    const int tb = blockIdx.x * 64;

    // ---- stage pre-split W [n][k] into smem (hi plane + lo plane) ----
#pragma unroll
    for (int it = 0; it < 8; it++) {
        int idx = it * 256 + tid;
        int n = idx >> 4;
        int k8 = (idx & 15) << 3;
        uint4 hv = *(const uint4*)(Whi + (size_t)n * Hh + k8);
        uint4 lv = *(const uint4*)(Wlo + (size_t)n * Hh + k8);
        *(uint4*)&sm[n * STRIDE + k8] = hv;
        *(uint4*)&sm[BLO_ELEM + n * STRIDE + k8] = lv;
    }

    // ---- per-thread fragment geometry ----
    const int wr = wid & 1;             // row band (x32 rows)
    const int wc = wid >> 1;            // col group (x32 cols)
    const int g = lane >> 2;
    const int tig = lane & 3;

    int grow[4];
    bool gv[4];
    const float* Ap[4];
#pragma unroll
    for (int j = 0; j < 4; j++) {
        grow[j] = tb + wr * 32 + j * 8 + g;
        gv[j] = grow[j] < M;
        Ap[j] = A + (size_t)(gv[j] ? grow[j] : 0) * Hh + 2 * tig;
    }

    // ldmatrix per-thread row address component (16-col x 16-k block)
    const int mq = lane >> 3;           // 0..3 (matrix select)
    const int tr = lane & 7;
    const uint32_t smem_u32 = smem_to_u32(sm);
    const uint32_t brow_off = (uint32_t)((((mq >> 1) * 8 + tr) * STRIDE + (mq & 1) * 8) * 2);
    const uint32_t colb = (uint32_t)(wc * 32 * STRIDE * 2);   // warp's 32-col group

    float c[2][4][4];
#pragma unroll
    for (int m = 0; m < 2; m++)
#pragma unroll
        for (int n = 0; n < 4; n++)
#pragma unroll
            for (int j = 0; j < 4; j++) c[m][n][j] = 0.f;

    __syncthreads();

#pragma unroll 1
    for (int k = 0; k < 8; k++) {
        int off = k << 4;
        // load A fp32 (issue all 8 LDG.64 up front)
        float2 f0[4], f1[4];
#pragma unroll
        for (int j = 0; j < 4; j++) {
            f0[j] = *(const float2*)(Ap[j] + off);
            f1[j] = *(const float2*)(Ap[j] + off + 8);
        }
        uint32_t ahA[4], alA[4], ahB[4], alB[4];
#pragma unroll
        for (int j = 0; j < 4; j++) {
            packsplit(f0[j], ahA[j], alA[j]);
            packsplit(f1[j], ahB[j], alB[j]);
        }
        const uint32_t kb = smem_u32 + brow_off + colb + ((uint32_t)k << 5);
#pragma unroll
        for (int n2 = 0; n2 < 2; n2++) {
            uint32_t ha = kb + (uint32_t)(n2 * 16 * STRIDE * 2);
            uint32_t la = ha + BLO_ELEM * 2;
            uint32_t bh0, bh1, bh2, bh3, bl0, bl1, bl2, bl3;
            LDSM4(bh0, bh1, bh2, bh3, ha);
            LDSM4(bl0, bl1, bl2, bl3, la);
#pragma unroll
            for (int m = 0; m < 2; m++) {
                uint32_t a0 = ahA[2 * m], a1 = ahA[2 * m + 1];
                uint32_t a2 = ahB[2 * m], a3 = ahB[2 * m + 1];
                uint32_t q0 = alA[2 * m], q1 = alA[2 * m + 1];
                uint32_t q2 = alB[2 * m], q3 = alB[2 * m + 1];
                mma16816(c[m][2 * n2], a0, a1, a2, a3, bh0, bh1);
                mma16816(c[m][2 * n2], a0, a1, a2, a3, bl0, bl1);
                mma16816(c[m][2 * n2], q0, q1, q2, q3, bh0, bh1);
                mma16816(c[m][2 * n2 + 1], a0, a1, a2, a3, bh2, bh3);
                mma16816(c[m][2 * n2 + 1], a0, a1, a2, a3, bl2, bl3);
                mma16816(c[m][2 * n2 + 1], q0, q1, q2, q3, bh2, bh3);
            }
        }
    }

    // ---- epilogue ----
    int gc[4] = {0, 0, 0, 0};
    if (EPI == 0 || EPI == 2) {
#pragma unroll
        for (int j = 0; j < 4; j++)
            if (gv[j]) gc[j] = batch[grow[j]];
    }
#pragma unroll
    for (int m = 0; m < 2; m++) {
        int j0 = 2 * m, j1 = 2 * m + 1;
#pragma unroll
        for (int n = 0; n < 4; n++) {
            int col = wc * 32 + (n << 3) + 2 * tig;
            float2 bv = *(const float2*)(bias + col);
            float o0x = c[m][n][0] + bv.x, o0y = c[m][n][1] + bv.y;
            float o1x = c[m][n][2] + bv.x, o1y = c[m][n][3] + bv.y;
            if (EPI == 0) {
                if (gv[j0]) {
                    float2 vv = *(const float2*)(vn + gc[j0] * Hh + col);
                    o0x += vv.x; o0y += vv.y;
                }
                if (gv[j1]) {
                    float2 vv = *(const float2*)(vn + gc[j1] * Hh + col);
                    o1x += vv.x; o1y += vv.y;
                }
            } else {
                o0x = fmaxf(o0x, 0.f); o0y = fmaxf(o0y, 0.f);
                o1x = fmaxf(o1x, 0.f); o1y = fmaxf(o1y, 0.f);
            }
            if (gv[j0]) {
                *(float2*)(C + (size_t)grow[j0] * Hh + col) = make_float2(o0x, o0y);
                if (EPI == 2) {
                    atomicAdd(&pooled[gc[j0] * Hh + col], o0x);
                    atomicAdd(&pooled[gc[j0] * Hh + col + 1], o0y);
                }
            }
            if (gv[j1]) {
                *(float2*)(C + (size_t)grow[j1] * Hh + col) = make_float2(o1x, o1y);
                if (EPI == 2) {
                    atomicAdd(&pooled[gc[j1] * Hh + col], o1x);
                    atomicAdd(&pooled[gc[j1] * Hh + col + 1], o1y);
                }
            }
        }
    }
}

// ======================= SpMM =======================
__launch_bounds__(256)
__global__ void spmm(const float* __restrict__ h, const float* __restrict__ eW,
                     const float* __restrict__ eb, float* __restrict__ agg) {
    __shared__ float sW[EDdim * Hh];
    for (int i = threadIdx.x; i < EDdim * Hh; i += 256) sW[i] = eW[i];
    __syncthreads();
    int warp = (blockIdx.x * 256 + threadIdx.x) >> 5;
    int lane = threadIdx.x & 31;
    if (warp >= NN) return;
    const int row = warp;
    const int c4 = lane << 2;

    float4 acc = make_float4(0.f, 0.f, 0.f, 0.f);
    const float* ea = g_eagg + row * EDdim;
#pragma unroll
    for (int k = 0; k < EDdim; k++) {
        float v = ea[k];
        float4 w = *(const float4*)&sW[k * Hh + c4];
        acc.x = fmaf(v, w.x, acc.x);
        acc.y = fmaf(v, w.y, acc.y);
        acc.z = fmaf(v, w.z, acc.z);
        acc.w = fmaf(v, w.w, acc.w);
    }
    int beg = g_rowptr[row];
    int end = g_rowptr[row + 1];
    float degf = (float)(end - beg);
    float4 bb = *(const float4*)(eb + c4);
    acc.x = fmaf(degf, bb.x, acc.x);
    acc.y = fmaf(degf, bb.y, acc.y);
    acc.z = fmaf(degf, bb.z, acc.z);
    acc.w = fmaf(degf, bb.w, acc.w);

    int e = beg;
    for (; e + 1 < end; e += 2) {
        int s0 = g_srcA[e];
        int s1 = g_srcA[e + 1];
        float4 h0 = *(const float4*)(h + (size_t)s0 * Hh + c4);
        float4 h1 = *(const float4*)(h + (size_t)s1 * Hh + c4);
        acc.x += h0.x + h1.x;
        acc.y += h0.y + h1.y;
        acc.z += h0.z + h1.z;
        acc.w += h0.w + h1.w;
    }
    if (e < end) {
        int s0 = g_srcA[e];
        float4 h0 = *(const float4*)(h + (size_t)s0 * Hh + c4);
        acc.x += h0.x;
        acc.y += h0.y;
        acc.z += h0.z;
        acc.w += h0.w;
    }
    *(float4*)(agg + (size_t)row * Hh + c4) = acc;
}

// ======================= small dense tails =======================
__global__ void vn_update(const float* __restrict__ w0, const float* __restrict__ b0,
                          const float* __restrict__ w1, const float* __restrict__ b1) {
    __shared__ float p[Hh];
    __shared__ float r0[Hh];
    int g = blockIdx.x, j = threadIdx.x;
    float cnt = fmaxf(g_counts[g], 1.f);
    p[j] = g_pooled[g * Hh + j] / cnt;
    __syncthreads();
    float s = b0[j];
    for (int k = 0; k < Hh; k++) s = fmaf(p[k], w0[k * Hh + j], s);
    r0[j] = fmaxf(s, 0.f);
    __syncthreads();
    float s2 = b1[j];
    for (int k = 0; k < Hh; k++) s2 = fmaf(r0[k], w1[k * Hh + j], s2);
    g_vn[g * Hh + j] += fmaxf(s2, 0.f);
}

__global__ void final_fc(const float* __restrict__ fcW, const float* __restrict__ fcb,
                         float* __restrict__ out) {
    __shared__ float p[Hh];
    int g = blockIdx.x, j = threadIdx.x;
    float cnt = fmaxf(g_counts[g], 1.f);
    p[j] = g_pooled[g * Hh + j] / cnt;
    __syncthreads();
    float s = fcb[j];
    for (int k = 0; k < Hh; k++) s = fmaf(p[k], fcW[k * Hh + j], s);
    out[g * Hh + j] = s;
}

// ======================= launch =======================
extern "C" void kernel_launch(void* const* d_in, const int* in_sizes, int n_in,
                              void* d_out, int out_size) {
    const float* x      = (const float*)d_in[0];
    const float* eattr  = (const float*)d_in[1];
    const float* nodeW  = (const float*)d_in[2];
    const float* nodeB  = (const float*)d_in[3];
    const float* edgeW  = (const float*)d_in[4];
    const float* edgeB  = (const float*)d_in[5];
    const float* m1W    = (const float*)d_in[6];
    const float* m1B    = (const float*)d_in[7];
    const float* m2W    = (const float*)d_in[8];
    const float* m2B    = (const float*)d_in[9];
    const float* vnw0   = (const float*)d_in[10];
    const float* vnb0   = (const float*)d_in[11];
    const float* vnw1   = (const float*)d_in[12];
    const float* vnb1   = (const float*)d_in[13];
    const float* fcW    = (const float*)d_in[14];
    const float* fcB    = (const float*)d_in[15];
    const float* vninit = (const float*)d_in[16];
    const int*   eidx   = (const int*)d_in[17];
    const int*   batch  = (const int*)d_in[18];
    const int* srcp = eidx;
    const int* dstp = eidx + EE;
    float* out = (float*)d_out;

    void *p_deg, *p_counts, *p_pooled, *p_x, *p_h, *p_agg, *p_vn, *p_whi, *p_wlo;
    cudaGetSymbolAddress(&p_deg, g_deg);
    cudaGetSymbolAddress(&p_counts, g_counts);
    cudaGetSymbolAddress(&p_pooled, g_pooled);
    cudaGetSymbolAddress(&p_x, g_x);
    cudaGetSymbolAddress(&p_h, g_h);
    cudaGetSymbolAddress(&p_agg, g_agg);
    cudaGetSymbolAddress(&p_vn, g_vn);
    cudaGetSymbolAddress(&p_whi, g_whi);
    cudaGetSymbolAddress(&p_wlo, g_wlo);

    cudaFuncSetAttribute(gemm_tc<0>, cudaFuncAttributeMaxDynamicSharedMemorySize, GEMM_SMEM);
    cudaFuncSetAttribute(gemm_tc<1>, cudaFuncAttributeMaxDynamicSharedMemorySize, GEMM_SMEM);
    cudaFuncSetAttribute(gemm_tc<2>, cudaFuncAttributeMaxDynamicSharedMemorySize, GEMM_SMEM);

    const __nv_bfloat16* whi = (const __nv_bfloat16*)p_whi;
    const __nv_bfloat16* wlo = (const __nv_bfloat16*)p_wlo;

    // launches 1..5 (memsets count), so first GEMM is #6 for the ncu window
    cudaMemsetAsync(p_deg, 0, sizeof(int) * NN);           // 1
    cudaMemsetAsync(p_counts, 0, sizeof(float) * Bb);      // 2
    k_wsplit<<<960, 256>>>(nodeW, m1W, m2W);               // 3
    k_vn_init<<<Bb, Hh>>>(vninit);                         // 4
    k_counts<<<(NN + 255) / 256, 256>>>(batch);            // 5
    gemm_tc<0><<<GBLK2, 256, GEMM_SMEM>>>(x, whi, wlo, nodeB,   // 6  <- profiled
                                          (float*)p_h, batch, (const float*)p_vn, nullptr, NN);

    // CSR build (independent of gemm0)
    k_deg<<<(EE + 255) / 256, 256>>>(dstp);
    k_bsum<<<NBLK, 256>>>();
    k_bscan<<<1, 256>>>();
    k_bfill<<<NBLK, 256>>>();
    k_fill<<<(EE + 255) / 256, 256>>>(srcp, dstp);
    k_eagg<<<(NN + 7) / 8, 256>>>(eattr);

    const int SPB = (NN + 7) / 8;

    for (int l = 0; l < Ll; l++) {
        if (l > 0) {
            gemm_tc<0><<<GBLK2, 256, GEMM_SMEM>>>((const float*)p_x, whi + (size_t)l * Hh * Hh,
                                                  wlo + (size_t)l * Hh * Hh, nodeB + l * Hh,
                                                  (float*)p_h, batch, (const float*)p_vn, nullptr, NN);
        }
        spmm<<<SPB, 256>>>((const float*)p_h, edgeW + (size_t)l * EDdim * Hh,
                           edgeB + l * Hh, (float*)p_agg);
        cudaMemsetAsync(p_pooled, 0, sizeof(float) * Bb * Hh);
        gemm_tc<1><<<GBLK2, 256, GEMM_SMEM>>>((const float*)p_agg, whi + (size_t)(5 + l) * Hh * Hh,
                                              wlo + (size_t)(5 + l) * Hh * Hh, m1B + l * Hh,
                                              (float*)p_h, nullptr, nullptr, nullptr, NN);
        gemm_tc<2><<<GBLK2, 256, GEMM_SMEM>>>((const float*)p_h, whi + (size_t)(10 + l) * Hh * Hh,
                                              wlo + (size_t)(10 + l) * Hh * Hh, m2B + l * Hh,
                                              (float*)p_x, batch, nullptr, (float*)p_pooled, NN);
        if (l < Ll - 1) vn_update<<<Bb, Hh>>>(vnw0, vnb0, vnw1, vnb1);
    }
    final_fc<<<Bb, Hh>>>(fcW, fcB, out);
}

// round 10
// speedup vs baseline: 1.5078x; 1.5078x over previous
#include <cuda_runtime.h>
#include <cuda_bf16.h>
#include <stdint.h>

#define NN 50000
#define EE 600000
#define Hh 128
#define EDdim 16
#define Bb 256
#define Ll 5
#define NBLK 196                    // ceil(NN/256)
#define GBLK ((NN + 127) / 128)     // 391 dense CTAs (128 rows)
#define STRIDE 136                  // padded bf16 row stride in smem (ldmatrix + LDS safe)
#define PLANE (128 * STRIDE)        // elems per plane
#define GEMM_SMEM (2 * PLANE * 2)   // prologue: W hi+lo = 69,632 B
#define FUSED_SMEM (6 * PLANE * 2)  // W + buf1 + buf2 (hi/lo each) = 208,896 B

// ======================= device scratch =======================
__device__ float g_h[(size_t)NN * Hh];            // hbar = x@nW (fp32, spmm gathers)
__device__ __nv_bfloat16 g_aggh[(size_t)NN * Hh]; // spmm out planes
__device__ __nv_bfloat16 g_aggl[(size_t)NN * Hh];
__device__ __nv_bfloat16 g_xhi[(size_t)NN * Hh];  // xn planes (unused by compute, kept for debug)
__device__ __nv_bfloat16 g_xlo[(size_t)NN * Hh];
__device__ float g_eagg[(size_t)NN * EDdim];
__device__ int   g_deg[NN];
__device__ int   g_rowptr[NN + 1];
__device__ int   g_cursor[NN];
__device__ int   g_srcA[EE];
__device__ int   g_eidA[EE];
__device__ int   g_gsrc[EE];                      // batch[src] per CSR slot
__device__ int   g_bsum[NBLK];
__device__ int   g_boff[NBLK];
__device__ float g_counts[Bb];
__device__ float g_pooled[Bb * Hh];
__device__ float g_vn[Bb * Hh];
__device__ __nv_bfloat16 g_whi[15 * Hh * Hh];     // [mat][n][k] transposed split
__device__ __nv_bfloat16 g_wlo[15 * Hh * Hh];

// pack float2 (v.x = even elem, v.y = odd elem) into bf16x2 hi + residual lo words
__device__ __forceinline__ void packsplit(float2 v, uint32_t& h, uint32_t& l) {
    uint32_t hp;
    asm("cvt.rn.bf16x2.f32 %0, %1, %2;" : "=r"(hp) : "f"(v.y), "f"(v.x));
    float h0 = __uint_as_float(hp << 16);
    float h1 = __uint_as_float(hp & 0xffff0000u);
    uint32_t lp;
    asm("cvt.rn.bf16x2.f32 %0, %1, %2;" : "=r"(lp) : "f"(v.y - h1), "f"(v.x - h0));
    h = hp;
    l = lp;
}

__device__ __forceinline__ void mma16816(float* c, uint32_t a0, uint32_t a1, uint32_t a2,
                                         uint32_t a3, uint32_t b0, uint32_t b1) {
    asm volatile(
        "mma.sync.aligned.m16n8k16.row.col.f32.bf16.bf16.f32 "
        "{%0,%1,%2,%3}, {%4,%5,%6,%7}, {%8,%9}, {%0,%1,%2,%3};"
        : "+f"(c[0]), "+f"(c[1]), "+f"(c[2]), "+f"(c[3])
        : "r"(a0), "r"(a1), "r"(a2), "r"(a3), "r"(b0), "r"(b1));
}

#define LDSM4(r0, r1, r2, r3, addr) \
    asm volatile("ldmatrix.sync.aligned.m8n8.x4.shared.b16 {%0,%1,%2,%3}, [%4];" \
                 : "=r"(r0), "=r"(r1), "=r"(r2), "=r"(r3) : "r"(addr))

__device__ __forceinline__ uint32_t smem_to_u32(const void* p) {
    uint32_t a;
    asm("{ .reg .u64 t; cvta.to.shared.u64 t, %1; cvt.u32.u64 %0, t; }" : "=r"(a) : "l"(p));
    return a;
}

// ======================= preprocessing =======================
__global__ void k_wsplit(const float* __restrict__ nodeW, const float* __restrict__ m1W,
                         const float* __restrict__ m2W) {
    int b = blockIdx.x;
    int mat = b >> 6;
    int idx = ((b & 63) << 8) + threadIdx.x;
    const float* Wsrc = (mat < 5) ? (nodeW + (size_t)mat * Hh * Hh)
                      : (mat < 10) ? (m1W + (size_t)(mat - 5) * Hh * Hh)
                      : (m2W + (size_t)(mat - 10) * Hh * Hh);
    int n = idx >> 7, k = idx & 127;
    float w = Wsrc[k * Hh + n];
    __nv_bfloat16 hi = __float2bfloat16(w);
    __nv_bfloat16 lo = __float2bfloat16(w - __bfloat162float(hi));
    g_whi[(size_t)mat * Hh * Hh + idx] = hi;
    g_wlo[(size_t)mat * Hh * Hh + idx] = lo;
}

__global__ void k_vn_init(const float* __restrict__ vninit) {
    g_vn[blockIdx.x * Hh + threadIdx.x] = vninit[threadIdx.x];
}

__global__ void k_counts(const int* __restrict__ batch) {
    int i = blockIdx.x * 256 + threadIdx.x;
    if (i < NN) atomicAdd(&g_counts[batch[i]], 1.0f);
}

__global__ void k_deg(const int* __restrict__ dst) {
    int e = blockIdx.x * 256 + threadIdx.x;
    if (e < EE) atomicAdd(&g_deg[dst[e]], 1);
}

__global__ void k_bsum() {
    __shared__ int s[256];
    int t = threadIdx.x;
    int i = blockIdx.x * 256 + t;
    s[t] = (i < NN) ? g_deg[i] : 0;
    __syncthreads();
    for (int o = 128; o > 0; o >>= 1) {
        if (t < o) s[t] += s[t + o];
        __syncthreads();
    }
    if (t == 0) g_bsum[blockIdx.x] = s[0];
}

__global__ void k_bscan() {
    __shared__ int s[256];
    int t = threadIdx.x;
    int v = (t < NBLK) ? g_bsum[t] : 0;
    s[t] = v;
    __syncthreads();
    for (int o = 1; o < 256; o <<= 1) {
        int u = (t >= o) ? s[t - o] : 0;
        __syncthreads();
        s[t] += u;
        __syncthreads();
    }
    if (t < NBLK) g_boff[t] = s[t] - v;
    if (t == 255) g_rowptr[NN] = s[255];
}

__global__ void k_bfill() {
    __shared__ int s[256];
    int t = threadIdx.x;
    int i = blockIdx.x * 256 + t;
    int v = (i < NN) ? g_deg[i] : 0;
    s[t] = v;
    __syncthreads();
    for (int o = 1; o < 256; o <<= 1) {
        int u = (t >= o) ? s[t - o] : 0;
        __syncthreads();
        s[t] += u;
        __syncthreads();
    }
    if (i < NN) {
        int pos = g_boff[blockIdx.x] + s[t] - v;
        g_rowptr[i] = pos;
        g_cursor[i] = pos;
    }
}

__global__ void k_fill(const int* __restrict__ src, const int* __restrict__ dst,
                       const int* __restrict__ batch) {
    int e = blockIdx.x * 256 + threadIdx.x;
    if (e >= EE) return;
    int d = dst[e];
    int s = src[e];
    int pos = atomicAdd(&g_cursor[d], 1);
    g_srcA[pos] = s;
    g_eidA[pos] = e;
    g_gsrc[pos] = batch[s];
}

__global__ void k_eagg(const float* __restrict__ eattr) {
    int w = (blockIdx.x * 256 + threadIdx.x) >> 5;
    int lane = threadIdx.x & 31;
    if (w >= NN || lane >= EDdim) return;
    int beg = g_rowptr[w], end = g_rowptr[w + 1];
    float s = 0.f;
    for (int e = beg; e < end; e++) {
        int eid = g_eidA[e];
        s += eattr[(size_t)eid * EDdim + lane];
    }
    g_eagg[w * EDdim + lane] = s;
}

// ======================= prologue GEMM: hbar0 = x @ nW0 (plain fp32 out) =======================
__launch_bounds__(256, 2)
__global__ void gemm_plain(const float* __restrict__ A, const __nv_bfloat16* __restrict__ Whi,
                           const __nv_bfloat16* __restrict__ Wlo, float* __restrict__ C, int M) {
    extern __shared__ __nv_bfloat16 sm[];
    const int tid = threadIdx.x;
    const int wid = tid >> 5;
    const int lane = tid & 31;
    const int tb = blockIdx.x * 128;

#pragma unroll
    for (int it = 0; it < 8; it++) {
        int idx = it * 256 + tid;
        int n = idx >> 4;
        int k8 = (idx & 15) << 3;
        uint4 hv = *(const uint4*)(Whi + (size_t)n * Hh + k8);
        uint4 lv = *(const uint4*)(Wlo + (size_t)n * Hh + k8);
        *(uint4*)&sm[n * STRIDE + k8] = hv;
        *(uint4*)&sm[PLANE + n * STRIDE + k8] = lv;
    }

    const int wr = wid & 3;
    const int wc = wid >> 2;
    const int g = lane >> 2;
    const int tig = lane & 3;

    int grow[4];
    bool gv[4];
    const float* Ap[4];
#pragma unroll
    for (int j = 0; j < 4; j++) {
        grow[j] = tb + wr * 32 + j * 8 + g;
        gv[j] = grow[j] < M;
        Ap[j] = A + (size_t)(gv[j] ? grow[j] : 0) * Hh + 2 * tig;
    }

    const int mq = lane >> 3;
    const int tr = lane & 7;
    const uint32_t smem_u32 = smem_to_u32(sm);
    const uint32_t brow_off = (uint32_t)((((mq >> 1) * 8 + tr) * STRIDE + (mq & 1) * 8) * 2);
    const uint32_t colb = (uint32_t)(wc * 64 * STRIDE * 2);

    float c[2][8][4];
#pragma unroll
    for (int m = 0; m < 2; m++)
#pragma unroll
        for (int n = 0; n < 8; n++)
#pragma unroll
            for (int j = 0; j < 4; j++) c[m][n][j] = 0.f;

    float2 pa[4][2];
#pragma unroll
    for (int j = 0; j < 4; j++) {
        pa[j][0] = *(const float2*)(Ap[j]);
        pa[j][1] = *(const float2*)(Ap[j] + 8);
    }
    __syncthreads();

#pragma unroll 1
    for (int k = 0; k < 8; k++) {
        uint32_t ahA[4], alA[4], ahB[4], alB[4];
#pragma unroll
        for (int j = 0; j < 4; j++) {
            packsplit(pa[j][0], ahA[j], alA[j]);
            packsplit(pa[j][1], ahB[j], alB[j]);
        }
        if (k < 7) {
            int off = (k + 1) << 4;
#pragma unroll
            for (int j = 0; j < 4; j++) {
                pa[j][0] = *(const float2*)(Ap[j] + off);
                pa[j][1] = *(const float2*)(Ap[j] + off + 8);
            }
        }
        const uint32_t kb = smem_u32 + brow_off + colb + ((uint32_t)k << 5);
#pragma unroll
        for (int n2 = 0; n2 < 4; n2++) {
            uint32_t ha = kb + (uint32_t)(n2 * 16 * STRIDE * 2);
            uint32_t la = ha + PLANE * 2;
            uint32_t bh0, bh1, bh2, bh3, bl0, bl1, bl2, bl3;
            LDSM4(bh0, bh1, bh2, bh3, ha);
            LDSM4(bl0, bl1, bl2, bl3, la);
#pragma unroll
            for (int m = 0; m < 2; m++) {
                uint32_t a0 = ahA[2 * m], a1 = ahA[2 * m + 1];
                uint32_t a2 = ahB[2 * m], a3 = ahB[2 * m + 1];
                uint32_t q0 = alA[2 * m], q1 = alA[2 * m + 1];
                uint32_t q2 = alB[2 * m], q3 = alB[2 * m + 1];
                mma16816(c[m][2 * n2], a0, a1, a2, a3, bh0, bh1);
                mma16816(c[m][2 * n2], a0, a1, a2, a3, bl0, bl1);
                mma16816(c[m][2 * n2], q0, q1, q2, q3, bh0, bh1);
                mma16816(c[m][2 * n2 + 1], a0, a1, a2, a3, bh2, bh3);
                mma16816(c[m][2 * n2 + 1], a0, a1, a2, a3, bl2, bl3);
                mma16816(c[m][2 * n2 + 1], q0, q1, q2, q3, bh2, bh3);
            }
        }
    }

#pragma unroll
    for (int m = 0; m < 2; m++) {
        int j0 = 2 * m, j1 = 2 * m + 1;
#pragma unroll
        for (int n = 0; n < 8; n++) {
            int col = wc * 64 + (n << 3) + 2 * tig;
            if (gv[j0])
                *(float2*)(C + (size_t)grow[j0] * Hh + col) = make_float2(c[m][n][0], c[m][n][1]);
            if (gv[j1])
                *(float2*)(C + (size_t)grow[j1] * Hh + col) = make_float2(c[m][n][2], c[m][n][3]);
        }
    }
}

// ======================= SpMM: agg planes = Σ hbar[src] + vn[batch[src]] + eagg@eW + deg*(eb+nb)
__launch_bounds__(256)
__global__ void spmm(const float* __restrict__ h, const float* __restrict__ eW,
                     const float* __restrict__ eb, const float* __restrict__ nb) {
    __shared__ float sW[EDdim * Hh];
    for (int i = threadIdx.x; i < EDdim * Hh; i += 256) sW[i] = eW[i];
    __syncthreads();
    int warp = (blockIdx.x * 256 + threadIdx.x) >> 5;
    int lane = threadIdx.x & 31;
    if (warp >= NN) return;
    const int row = warp;
    const int c4 = lane << 2;

    float4 acc = make_float4(0.f, 0.f, 0.f, 0.f);
    const float* ea = g_eagg + row * EDdim;
#pragma unroll
    for (int k = 0; k < EDdim; k++) {
        float v = ea[k];
        float4 w = *(const float4*)&sW[k * Hh + c4];
        acc.x = fmaf(v, w.x, acc.x);
        acc.y = fmaf(v, w.y, acc.y);
        acc.z = fmaf(v, w.z, acc.z);
        acc.w = fmaf(v, w.w, acc.w);
    }
    int beg = g_rowptr[row];
    int end = g_rowptr[row + 1];
    float degf = (float)(end - beg);
    float4 bb = *(const float4*)(eb + c4);
    float4 nbv = *(const float4*)(nb + c4);
    acc.x = fmaf(degf, bb.x + nbv.x, acc.x);
    acc.y = fmaf(degf, bb.y + nbv.y, acc.y);
    acc.z = fmaf(degf, bb.z + nbv.z, acc.z);
    acc.w = fmaf(degf, bb.w + nbv.w, acc.w);

    for (int e = beg; e < end; e++) {
        int s0 = g_srcA[e];
        int ge = g_gsrc[e];
        float4 h0 = *(const float4*)(h + (size_t)s0 * Hh + c4);
        float4 v0 = *(const float4*)(g_vn + (size_t)ge * Hh + c4);
        acc.x += h0.x + v0.x;
        acc.y += h0.y + v0.y;
        acc.z += h0.z + v0.z;
        acc.w += h0.w + v0.w;
    }
    uint32_t h0w, l0w, h1w, l1w;
    packsplit(make_float2(acc.x, acc.y), h0w, l0w);
    packsplit(make_float2(acc.z, acc.w), h1w, l1w);
    *(uint2*)(g_aggh + (size_t)row * Hh + c4) = make_uint2(h0w, h1w);
    *(uint2*)(g_aggl + (size_t)row * Hh + c4) = make_uint2(l0w, l1w);
}

// ======================= FUSED dense layer: mlp1 -> mlp2 -> node-encode(next) ==============
// 512 threads, 1 CTA/SM, 128-row tile. smem: Wbuf(2 planes) + buf1(2) + buf2(2).
// phase1: t1 = relu(agg@m1W + b1)   [A: gmem planes -> buf1 smem]
// phase2: xn = relu(t1@m2W + b2)    [A: buf1 -> buf2 smem + pooled atomics]
// phase3: hbar = xn@nW              [A: buf2 -> fp32 gmem]  (skipped if LAST)
#define WOFF 0
#define B1OFF (2 * PLANE)
#define B2OFF (4 * PLANE)

template <bool LAST>
__launch_bounds__(512, 1)
__global__ void fused_layer(const __nv_bfloat16* __restrict__ w1h, const __nv_bfloat16* __restrict__ w1l,
                            const __nv_bfloat16* __restrict__ w2h, const __nv_bfloat16* __restrict__ w2l,
                            const __nv_bfloat16* __restrict__ wnh, const __nv_bfloat16* __restrict__ wnl,
                            const float* __restrict__ b1, const float* __restrict__ b2,
                            const int* __restrict__ batch, float* __restrict__ pooled,
                            float* __restrict__ hbar, int M) {
    extern __shared__ __nv_bfloat16 sm[];
    const int tid = threadIdx.x;
    const int wid = tid >> 5;
    const int lane = tid & 31;
    const int tb = blockIdx.x * 128;

    const int wr = wid & 7;             // 8 row bands x 16 rows
    const int wc = wid >> 3;            // 2 col halves x 64
    const int g = lane >> 2;
    const int tig = lane & 3;
    const int r0 = wr * 16 + g;
    const int r1 = r0 + 8;
    const int grow0 = tb + r0;
    const int grow1 = tb + r1;
    const bool v0 = grow0 < M, v1 = grow1 < M;
    const int cr0 = v0 ? grow0 : 0;
    const int cr1 = v1 ? grow1 : 0;

    const int mq = lane >> 3;
    const int tr = lane & 7;
    const uint32_t smem_u32 = smem_to_u32(sm);
    const uint32_t brow_off = (uint32_t)((((mq >> 1) * 8 + tr) * STRIDE + (mq & 1) * 8) * 2);
    const uint32_t colb = (uint32_t)(wc * 64 * STRIDE * 2);
    const uint32_t wb_base = smem_u32 + brow_off + colb;   // Wbuf at offset 0

    // ---- stage m1W ----
#pragma unroll
    for (int it = 0; it < 4; it++) {
        int idx = it * 512 + tid;
        int n = idx >> 4;
        int k8 = (idx & 15) << 3;
        *(uint4*)&sm[WOFF + n * STRIDE + k8] = *(const uint4*)(w1h + (size_t)n * Hh + k8);
        *(uint4*)&sm[WOFF + PLANE + n * STRIDE + k8] = *(const uint4*)(w1l + (size_t)n * Hh + k8);
    }
    __syncthreads();

    float c[8][4];

    // ================= phase 1: A from gmem agg planes =================
#pragma unroll
    for (int n = 0; n < 8; n++)
#pragma unroll
        for (int j = 0; j < 4; j++) c[n][j] = 0.f;
    {
        const __nv_bfloat16* A0h = g_aggh + (size_t)cr0 * Hh + 2 * tig;
        const __nv_bfloat16* A1h = g_aggh + (size_t)cr1 * Hh + 2 * tig;
        const __nv_bfloat16* A0l = g_aggl + (size_t)cr0 * Hh + 2 * tig;
        const __nv_bfloat16* A1l = g_aggl + (size_t)cr1 * Hh + 2 * tig;
#pragma unroll 1
        for (int k = 0; k < 8; k++) {
            int off = k << 4;
            uint32_t ah0 = *(const uint32_t*)(A0h + off);
            uint32_t ah1 = *(const uint32_t*)(A1h + off);
            uint32_t ah2 = *(const uint32_t*)(A0h + off + 8);
            uint32_t ah3 = *(const uint32_t*)(A1h + off + 8);
            uint32_t al0 = *(const uint32_t*)(A0l + off);
            uint32_t al1 = *(const uint32_t*)(A1l + off);
            uint32_t al2 = *(const uint32_t*)(A0l + off + 8);
            uint32_t al3 = *(const uint32_t*)(A1l + off + 8);
            const uint32_t kb = wb_base + ((uint32_t)k << 5);
#pragma unroll
            for (int n2 = 0; n2 < 4; n2++) {
                uint32_t ha = kb + (uint32_t)(n2 * 16 * STRIDE * 2);
                uint32_t la = ha + PLANE * 2;
                uint32_t bh0, bh1, bh2, bh3, bl0, bl1, bl2, bl3;
                LDSM4(bh0, bh1, bh2, bh3, ha);
                LDSM4(bl0, bl1, bl2, bl3, la);
                mma16816(c[2 * n2], ah0, ah1, ah2, ah3, bh0, bh1);
                mma16816(c[2 * n2], ah0, ah1, ah2, ah3, bl0, bl1);
                mma16816(c[2 * n2], al0, al1, al2, al3, bh0, bh1);
                mma16816(c[2 * n2 + 1], ah0, ah1, ah2, ah3, bh2, bh3);
                mma16816(c[2 * n2 + 1], ah0, ah1, ah2, ah3, bl2, bl3);
                mma16816(c[2 * n2 + 1], al0, al1, al2, al3, bh2, bh3);
            }
        }
    }
    __syncthreads();   // all warps done reading m1W

    // stage m2W + write t1 into buf1
#pragma unroll
    for (int it = 0; it < 4; it++) {
        int idx = it * 512 + tid;
        int n = idx >> 4;
        int k8 = (idx & 15) << 3;
        *(uint4*)&sm[WOFF + n * STRIDE + k8] = *(const uint4*)(w2h + (size_t)n * Hh + k8);
        *(uint4*)&sm[WOFF + PLANE + n * STRIDE + k8] = *(const uint4*)(w2l + (size_t)n * Hh + k8);
    }
#pragma unroll
    for (int n = 0; n < 8; n++) {
        int col = wc * 64 + (n << 3) + 2 * tig;
        float2 bv = *(const float2*)(b1 + col);
        float2 o0 = make_float2(fmaxf(c[n][0] + bv.x, 0.f), fmaxf(c[n][1] + bv.y, 0.f));
        float2 o1 = make_float2(fmaxf(c[n][2] + bv.x, 0.f), fmaxf(c[n][3] + bv.y, 0.f));
        uint32_t hw, lw;
        packsplit(o0, hw, lw);
        *(uint32_t*)&sm[B1OFF + r0 * STRIDE + col] = hw;
        *(uint32_t*)&sm[B1OFF + PLANE + r0 * STRIDE + col] = lw;
        packsplit(o1, hw, lw);
        *(uint32_t*)&sm[B1OFF + r1 * STRIDE + col] = hw;
        *(uint32_t*)&sm[B1OFF + PLANE + r1 * STRIDE + col] = lw;
    }
    __syncthreads();

    // ================= phase 2: A from buf1 =================
#pragma unroll
    for (int n = 0; n < 8; n++)
#pragma unroll
        for (int j = 0; j < 4; j++) c[n][j] = 0.f;
    {
        const int a0 = B1OFF + r0 * STRIDE + 2 * tig;
        const int a1 = B1OFF + r1 * STRIDE + 2 * tig;
#pragma unroll 1
        for (int k = 0; k < 8; k++) {
            int off = k << 4;
            uint32_t ah0 = *(const uint32_t*)&sm[a0 + off];
            uint32_t ah1 = *(const uint32_t*)&sm[a1 + off];
            uint32_t ah2 = *(const uint32_t*)&sm[a0 + off + 8];
            uint32_t ah3 = *(const uint32_t*)&sm[a1 + off + 8];
            uint32_t al0 = *(const uint32_t*)&sm[a0 + PLANE + off];
            uint32_t al1 = *(const uint32_t*)&sm[a1 + PLANE + off];
            uint32_t al2 = *(const uint32_t*)&sm[a0 + PLANE + off + 8];
            uint32_t al3 = *(const uint32_t*)&sm[a1 + PLANE + off + 8];
            const uint32_t kb = wb_base + ((uint32_t)k << 5);
#pragma unroll
            for (int n2 = 0; n2 < 4; n2++) {
                uint32_t ha = kb + (uint32_t)(n2 * 16 * STRIDE * 2);
                uint32_t la = ha + PLANE * 2;
                uint32_t bh0, bh1, bh2, bh3, bl0, bl1, bl2, bl3;
                LDSM4(bh0, bh1, bh2, bh3, ha);
                LDSM4(bl0, bl1, bl2, bl3, la);
                mma16816(c[2 * n2], ah0, ah1, ah2, ah3, bh0, bh1);
                mma16816(c[2 * n2], ah0, ah1, ah2, ah3, bl0, bl1);
                mma16816(c[2 * n2], al0, al1, al2, al3, bh0, bh1);
                mma16816(c[2 * n2 + 1], ah0, ah1, ah2, ah3, bh2, bh3);
                mma16816(c[2 * n2 + 1], ah0, ah1, ah2, ah3, bl2, bl3);
                mma16816(c[2 * n2 + 1], al0, al1, al2, al3, bh2, bh3);
            }
        }
    }
    __syncthreads();   // done reading m2W (and buf1)

    // stage nW (if needed) + write xn into buf2 + gmem planes + pooled atomics
    if (!LAST) {
#pragma unroll
        for (int it = 0; it < 4; it++) {
            int idx = it * 512 + tid;
            int n = idx >> 4;
            int k8 = (idx & 15) << 3;
            *(uint4*)&sm[WOFF + n * STRIDE + k8] = *(const uint4*)(wnh + (size_t)n * Hh + k8);
            *(uint4*)&sm[WOFF + PLANE + n * STRIDE + k8] = *(const uint4*)(wnl + (size_t)n * Hh + k8);
        }
    }
    {
        int gc0 = v0 ? batch[grow0] : 0;
        int gc1 = v1 ? batch[grow1] : 0;
#pragma unroll
        for (int n = 0; n < 8; n++) {
            int col = wc * 64 + (n << 3) + 2 * tig;
            float2 bv = *(const float2*)(b2 + col);
            float2 o0 = make_float2(fmaxf(c[n][0] + bv.x, 0.f), fmaxf(c[n][1] + bv.y, 0.f));
            float2 o1 = make_float2(fmaxf(c[n][2] + bv.x, 0.f), fmaxf(c[n][3] + bv.y, 0.f));
            uint32_t hw, lw;
            packsplit(o0, hw, lw);
            *(uint32_t*)&sm[B2OFF + r0 * STRIDE + col] = hw;
            *(uint32_t*)&sm[B2OFF + PLANE + r0 * STRIDE + col] = lw;
            packsplit(o1, hw, lw);
            *(uint32_t*)&sm[B2OFF + r1 * STRIDE + col] = hw;
            *(uint32_t*)&sm[B2OFF + PLANE + r1 * STRIDE + col] = lw;
            if (v0) {
                atomicAdd(&pooled[gc0 * Hh + col], o0.x);
                atomicAdd(&pooled[gc0 * Hh + col + 1], o0.y);
            }
            if (v1) {
                atomicAdd(&pooled[gc1 * Hh + col], o1.x);
                atomicAdd(&pooled[gc1 * Hh + col + 1], o1.y);
            }
        }
    }
    if (LAST) return;
    __syncthreads();

    // ================= phase 3: hbar = xn @ nW (plain fp32 out) =================
#pragma unroll
    for (int n = 0; n < 8; n++)
#pragma unroll
        for (int j = 0; j < 4; j++) c[n][j] = 0.f;
    {
        const int a0 = B2OFF + r0 * STRIDE + 2 * tig;
        const int a1 = B2OFF + r1 * STRIDE + 2 * tig;
#pragma unroll 1
        for (int k = 0; k < 8; k++) {
            int off = k << 4;
            uint32_t ah0 = *(const uint32_t*)&sm[a0 + off];
            uint32_t ah1 = *(const uint32_t*)&sm[a1 + off];
            uint32_t ah2 = *(const uint32_t*)&sm[a0 + off + 8];
            uint32_t ah3 = *(const uint32_t*)&sm[a1 + off + 8];
            uint32_t al0 = *(const uint32_t*)&sm[a0 + PLANE + off];
            uint32_t al1 = *(const uint32_t*)&sm[a1 + PLANE + off];
            uint32_t al2 = *(const uint32_t*)&sm[a0 + PLANE + off + 8];
            uint32_t al3 = *(const uint32_t*)&sm[a1 + PLANE + off + 8];
            const uint32_t kb = wb_base + ((uint32_t)k << 5);
#pragma unroll
            for (int n2 = 0; n2 < 4; n2++) {
                uint32_t ha = kb + (uint32_t)(n2 * 16 * STRIDE * 2);
                uint32_t la = ha + PLANE * 2;
                uint32_t bh0, bh1, bh2, bh3, bl0, bl1, bl2, bl3;
                LDSM4(bh0, bh1, bh2, bh3, ha);
                LDSM4(bl0, bl1, bl2, bl3, la);
                mma16816(c[2 * n2], ah0, ah1, ah2, ah3, bh0, bh1);
                mma16816(c[2 * n2], ah0, ah1, ah2, ah3, bl0, bl1);
                mma16816(c[2 * n2], al0, al1, al2, al3, bh0, bh1);
                mma16816(c[2 * n2 + 1], ah0, ah1, ah2, ah3, bh2, bh3);
                mma16816(c[2 * n2 + 1], ah0, ah1, ah2, ah3, bl2, bl3);
                mma16816(c[2 * n2 + 1], al0, al1, al2, al3, bh2, bh3);
            }
        }
    }
#pragma unroll
    for (int n = 0; n < 8; n++) {
        int col = wc * 64 + (n << 3) + 2 * tig;
        if (v0)
            *(float2*)(hbar + (size_t)grow0 * Hh + col) = make_float2(c[n][0], c[n][1]);
        if (v1)
            *(float2*)(hbar + (size_t)grow1 * Hh + col) = make_float2(c[n][2], c[n][3]);
    }
}

// ======================= small dense tails =======================
__global__ void vn_update(const float* __restrict__ w0, const float* __restrict__ b0,
                          const float* __restrict__ w1, const float* __restrict__ b1) {
    __shared__ float p[Hh];
    __shared__ float r0[Hh];
    int g = blockIdx.x, j = threadIdx.x;
    float cnt = fmaxf(g_counts[g], 1.f);
    p[j] = g_pooled[g * Hh + j] / cnt;
    __syncthreads();
    float s = b0[j];
    for (int k = 0; k < Hh; k++) s = fmaf(p[k], w0[k * Hh + j], s);
    r0[j] = fmaxf(s, 0.f);
    __syncthreads();
    float s2 = b1[j];
    for (int k = 0; k < Hh; k++) s2 = fmaf(r0[k], w1[k * Hh + j], s2);
    g_vn[g * Hh + j] += fmaxf(s2, 0.f);
}

__global__ void final_fc(const float* __restrict__ fcW, const float* __restrict__ fcb,
                         float* __restrict__ out) {
    __shared__ float p[Hh];
    int g = blockIdx.x, j = threadIdx.x;
    float cnt = fmaxf(g_counts[g], 1.f);
    p[j] = g_pooled[g * Hh + j] / cnt;
    __syncthreads();
    float s = fcb[j];
    for (int k = 0; k < Hh; k++) s = fmaf(p[k], fcW[k * Hh + j], s);
    out[g * Hh + j] = s;
}

// ======================= launch =======================
extern "C" void kernel_launch(void* const* d_in, const int* in_sizes, int n_in,
                              void* d_out, int out_size) {
    const float* x      = (const float*)d_in[0];
    const float* eattr  = (const float*)d_in[1];
    const float* nodeW  = (const float*)d_in[2];
    const float* nodeB  = (const float*)d_in[3];
    const float* edgeW  = (const float*)d_in[4];
    const float* edgeB  = (const float*)d_in[5];
    const float* m1W    = (const float*)d_in[6];
    const float* m1B    = (const float*)d_in[7];
    const float* m2W    = (const float*)d_in[8];
    const float* m2B    = (const float*)d_in[9];
    const float* vnw0   = (const float*)d_in[10];
    const float* vnb0   = (const float*)d_in[11];
    const float* vnw1   = (const float*)d_in[12];
    const float* vnb1   = (const float*)d_in[13];
    const float* fcW    = (const float*)d_in[14];
    const float* fcB    = (const float*)d_in[15];
    const float* vninit = (const float*)d_in[16];
    const int*   eidx   = (const int*)d_in[17];
    const int*   batch  = (const int*)d_in[18];
    const int* srcp = eidx;
    const int* dstp = eidx + EE;
    float* out = (float*)d_out;

    void *p_deg, *p_counts, *p_pooled, *p_h, *p_whi, *p_wlo;
    cudaGetSymbolAddress(&p_deg, g_deg);
    cudaGetSymbolAddress(&p_counts, g_counts);
    cudaGetSymbolAddress(&p_pooled, g_pooled);
    cudaGetSymbolAddress(&p_h, g_h);
    cudaGetSymbolAddress(&p_whi, g_whi);
    cudaGetSymbolAddress(&p_wlo, g_wlo);

    cudaFuncSetAttribute(gemm_plain, cudaFuncAttributeMaxDynamicSharedMemorySize, GEMM_SMEM);
    cudaFuncSetAttribute(fused_layer<false>, cudaFuncAttributeMaxDynamicSharedMemorySize, FUSED_SMEM);
    cudaFuncSetAttribute(fused_layer<true>, cudaFuncAttributeMaxDynamicSharedMemorySize, FUSED_SMEM);

    const __nv_bfloat16* whi = (const __nv_bfloat16*)p_whi;
    const __nv_bfloat16* wlo = (const __nv_bfloat16*)p_wlo;

    // launches 1..5, GEMM prologue at slot 6 for the ncu -s 5 -c 1 window
    cudaMemsetAsync(p_deg, 0, sizeof(int) * NN);           // 1
    cudaMemsetAsync(p_counts, 0, sizeof(float) * Bb);      // 2
    k_wsplit<<<960, 256>>>(nodeW, m1W, m2W);               // 3
    k_vn_init<<<Bb, Hh>>>(vninit);                         // 4
    k_counts<<<(NN + 255) / 256, 256>>>(batch);            // 5
    gemm_plain<<<GBLK, 256, GEMM_SMEM>>>(x, whi, wlo, (float*)p_h, NN);  // 6 <- profiled

    // CSR build
    k_deg<<<(EE + 255) / 256, 256>>>(dstp);
    k_bsum<<<NBLK, 256>>>();
    k_bscan<<<1, 256>>>();
    k_bfill<<<NBLK, 256>>>();
    k_fill<<<(EE + 255) / 256, 256>>>(srcp, dstp, batch);
    k_eagg<<<(NN + 7) / 8, 256>>>(eattr);

    const int SPB = (NN + 7) / 8;

    for (int l = 0; l < Ll; l++) {
        spmm<<<SPB, 256>>>((const float*)p_h, edgeW + (size_t)l * EDdim * Hh,
                           edgeB + l * Hh, nodeB + l * Hh);
        cudaMemsetAsync(p_pooled, 0, sizeof(float) * Bb * Hh);
        const __nv_bfloat16* w1h = whi + (size_t)(5 + l) * Hh * Hh;
        const __nv_bfloat16* w1l = wlo + (size_t)(5 + l) * Hh * Hh;
        const __nv_bfloat16* w2h = whi + (size_t)(10 + l) * Hh * Hh;
        const __nv_bfloat16* w2l = wlo + (size_t)(10 + l) * Hh * Hh;
        if (l < Ll - 1) {
            const __nv_bfloat16* wnh = whi + (size_t)(l + 1) * Hh * Hh;
            const __nv_bfloat16* wnl = wlo + (size_t)(l + 1) * Hh * Hh;
            fused_layer<false><<<GBLK, 512, FUSED_SMEM>>>(
                w1h, w1l, w2h, w2l, wnh, wnl, m1B + l * Hh, m2B + l * Hh,
                batch, (float*)p_pooled, (float*)p_h, NN);
            vn_update<<<Bb, Hh>>>(vnw0, vnb0, vnw1, vnb1);
        } else {
            fused_layer<true><<<GBLK, 512, FUSED_SMEM>>>(
                w1h, w1l, w2h, w2l, w1h, w1l, m1B + l * Hh, m2B + l * Hh,
                batch, (float*)p_pooled, (float*)p_h, NN);
        }
    }
    final_fc<<<Bb, Hh>>>(fcW, fcB, out);
}

// round 12
// speedup vs baseline: 1.5667x; 1.0390x over previous
#include <cuda_runtime.h>
#include <cuda_bf16.h>
#include <stdint.h>

#define NN 50000
#define EE 600000
#define Hh 128
#define EDdim 16
#define Bb 256
#define Ll 5
#define NBLK 196                    // ceil(NN/256)
#define NTILES ((NN + 127) / 128)   // 391 row tiles
#define PGRID 296                   // persistent grid = 148 SM x 2 CTA
#define STRIDE 136                  // padded bf16 row stride in smem
#define BLO_ELEM (128 * STRIDE)     // lo-plane offset in bf16 elems
#define GEMM_SMEM (2 * 128 * STRIDE * 2)   // B hi+lo: 69,632 bytes

// ======================= device scratch =======================
__device__ float g_x[(size_t)NN * Hh];
__device__ float g_h[(size_t)NN * Hh];
__device__ float g_agg[(size_t)NN * Hh];
__device__ float g_eagg[(size_t)NN * EDdim];
__device__ int   g_rowptr[NN + 1];
__device__ int   g_cursor[NN];
__device__ int   g_srcA[EE];
__device__ int   g_eidA[EE];
__device__ int   g_bsum[NBLK];
__device__ float g_vn[Bb * Hh];
__device__ __nv_bfloat16 g_whi[15 * Hh * Hh];  // [mat][n][k] transposed split
__device__ __nv_bfloat16 g_wlo[15 * Hh * Hh];

// all-zeroed-at-start scratch in ONE block (single memset)
struct ZeroBlk {
    int   deg[NN];
    float counts[Bb];
    float pooled[Ll][Bb * Hh];
};
__device__ ZeroBlk g_z;

// ======================= helpers =======================
__device__ __forceinline__ void packsplit(float2 v, uint32_t& h, uint32_t& l) {
    uint32_t hp;
    asm("cvt.rn.bf16x2.f32 %0, %1, %2;" : "=r"(hp) : "f"(v.y), "f"(v.x));
    float h0 = __uint_as_float(hp << 16);
    float h1 = __uint_as_float(hp & 0xffff0000u);
    uint32_t lp;
    asm("cvt.rn.bf16x2.f32 %0, %1, %2;" : "=r"(lp) : "f"(v.y - h1), "f"(v.x - h0));
    h = hp;
    l = lp;
}

__device__ __forceinline__ void mma16816(float* c, uint32_t a0, uint32_t a1, uint32_t a2,
                                         uint32_t a3, uint32_t b0, uint32_t b1) {
    asm volatile(
        "mma.sync.aligned.m16n8k16.row.col.f32.bf16.bf16.f32 "
        "{%0,%1,%2,%3}, {%4,%5,%6,%7}, {%8,%9}, {%0,%1,%2,%3};"
        : "+f"(c[0]), "+f"(c[1]), "+f"(c[2]), "+f"(c[3])
        : "r"(a0), "r"(a1), "r"(a2), "r"(a3), "r"(b0), "r"(b1));
}

#define LDSM4(r0, r1, r2, r3, addr) \
    asm volatile("ldmatrix.sync.aligned.m8n8.x4.shared.b16 {%0,%1,%2,%3}, [%4];" \
                 : "=r"(r0), "=r"(r1), "=r"(r2), "=r"(r3) : "r"(addr))

__device__ __forceinline__ uint32_t smem_to_u32(const void* p) {
    uint32_t a;
    asm("{ .reg .u64 t; cvta.to.shared.u64 t, %1; cvt.u32.u64 %0, t; }" : "=r"(a) : "l"(p));
    return a;
}

// ======================= preprocessing =======================
__global__ void k_wsplit(const float* __restrict__ nodeW, const float* __restrict__ m1W,
                         const float* __restrict__ m2W) {
    int b = blockIdx.x;
    int mat = b >> 6;
    int idx = ((b & 63) << 8) + threadIdx.x;
    const float* Wsrc = (mat < 5) ? (nodeW + (size_t)mat * Hh * Hh)
                      : (mat < 10) ? (m1W + (size_t)(mat - 5) * Hh * Hh)
                      : (m2W + (size_t)(mat - 10) * Hh * Hh);
    int n = idx >> 7, k = idx & 127;
    float w = Wsrc[k * Hh + n];
    __nv_bfloat16 hi = __float2bfloat16(w);
    __nv_bfloat16 lo = __float2bfloat16(w - __bfloat162float(hi));
    g_whi[(size_t)mat * Hh * Hh + idx] = hi;
    g_wlo[(size_t)mat * Hh * Hh + idx] = lo;
}

__global__ void k_vn_init(const float* __restrict__ vninit) {
    g_vn[blockIdx.x * Hh + threadIdx.x] = vninit[threadIdx.x];
}

__global__ void k_counts(const int* __restrict__ batch) {
    int i = blockIdx.x * 256 + threadIdx.x;
    if (i < NN) atomicAdd(&g_z.counts[batch[i]], 1.0f);
}

__global__ void k_deg(const int* __restrict__ dst) {
    int e = blockIdx.x * 256 + threadIdx.x;
    if (e < EE) atomicAdd(&g_z.deg[dst[e]], 1);
}

__global__ void k_bsum() {
    __shared__ int s[256];
    int t = threadIdx.x;
    int i = blockIdx.x * 256 + t;
    s[t] = (i < NN) ? g_z.deg[i] : 0;
    __syncthreads();
    for (int o = 128; o > 0; o >>= 1) {
        if (t < o) s[t] += s[t + o];
        __syncthreads();
    }
    if (t == 0) g_bsum[blockIdx.x] = s[0];
}

// merged inter-block prefix + local scan -> rowptr/cursor
__global__ void k_bscanfill() {
    __shared__ int s[256];
    __shared__ int base;
    int t = threadIdx.x;
    int p = 0;
    for (int i = t; i < (int)blockIdx.x; i += 256) p += g_bsum[i];
    s[t] = p;
    __syncthreads();
    for (int o = 128; o > 0; o >>= 1) {
        if (t < o) s[t] += s[t + o];
        __syncthreads();
    }
    if (t == 0) base = s[0];
    __syncthreads();
    int i = blockIdx.x * 256 + t;
    int v = (i < NN) ? g_z.deg[i] : 0;
    s[t] = v;
    __syncthreads();
    for (int o = 1; o < 256; o <<= 1) {
        int u = (t >= o) ? s[t - o] : 0;
        __syncthreads();
        s[t] += u;
        __syncthreads();
    }
    if (i < NN) {
        int pos = base + s[t] - v;
        g_rowptr[i] = pos;
        g_cursor[i] = pos;
    }
    if (blockIdx.x == NBLK - 1 && t == 255) g_rowptr[NN] = base + s[255];
}

__global__ void k_fill(const int* __restrict__ src, const int* __restrict__ dst) {
    int e = blockIdx.x * 256 + threadIdx.x;
    if (e >= EE) return;
    int d = dst[e];
    int pos = atomicAdd(&g_cursor[d], 1);
    g_srcA[pos] = src[e];
    g_eidA[pos] = e;
}

__global__ void k_eagg(const float* __restrict__ eattr) {
    int w = (blockIdx.x * 256 + threadIdx.x) >> 5;
    int lane = threadIdx.x & 31;
    if (w >= NN || lane >= EDdim) return;
    int beg = g_rowptr[w], end = g_rowptr[w + 1];
    float s = 0.f;
    for (int e = beg; e < end; e++) {
        int eid = g_eidA[e];
        s += eattr[(size_t)eid * EDdim + lane];
    }
    g_eagg[w * EDdim + lane] = s;
}

// ======================= persistent HMMA bf16-split GEMM =======================
// C[M,128] = A[M,128] @ W[128,128]; D = Ahi@Bhi + Ahi@Blo + Alo@Bhi (fp32 accum).
// Persistent: 296 CTAs loop over 391 row tiles; B staged ONCE per CTA.
// Warp grid 4(rows)x2(cols): warp tile 32x64.
// EPI 0: +bias +vn[batch]; EPI 1: relu(+bias); EPI 2: relu(+bias) + pooled atomic.
template <int EPI>
__launch_bounds__(256, 2)
__global__ void gemm_tc(const float* __restrict__ A, const __nv_bfloat16* __restrict__ Whi,
                        const __nv_bfloat16* __restrict__ Wlo, const float* __restrict__ bias,
                        float* __restrict__ C, const int* __restrict__ batch,
                        const float* __restrict__ vn, float* __restrict__ pooled, int M) {
    extern __shared__ __nv_bfloat16 sm[];
    const int tid = threadIdx.x;
    const int wid = tid >> 5;
    const int lane = tid & 31;

    // ---- stage pre-split W once ----
#pragma unroll
    for (int it = 0; it < 8; it++) {
        int idx = it * 256 + tid;
        int n = idx >> 4;
        int k8 = (idx & 15) << 3;
        uint4 hv = *(const uint4*)(Whi + (size_t)n * Hh + k8);
        uint4 lv = *(const uint4*)(Wlo + (size_t)n * Hh + k8);
        *(uint4*)&sm[n * STRIDE + k8] = hv;
        *(uint4*)&sm[BLO_ELEM + n * STRIDE + k8] = lv;
    }

    const int wr = wid & 3;
    const int wc = wid >> 2;
    const int g = lane >> 2;
    const int tig = lane & 3;

    const int mq = lane >> 3;
    const int tr = lane & 7;
    const uint32_t smem_u32 = smem_to_u32(sm);
    const uint32_t brow_off = (uint32_t)((((mq >> 1) * 8 + tr) * STRIDE + (mq & 1) * 8) * 2);
    const uint32_t colb = (uint32_t)(wc * 64 * STRIDE * 2);

    __syncthreads();

    for (int tile = blockIdx.x; tile < (M + 127) / 128; tile += gridDim.x) {
        const int tb = tile * 128;
        int grow[4];
        bool gv[4];
        const float* Ap[4];
#pragma unroll
        for (int j = 0; j < 4; j++) {
            grow[j] = tb + wr * 32 + j * 8 + g;
            gv[j] = grow[j] < M;
            Ap[j] = A + (size_t)(gv[j] ? grow[j] : 0) * Hh + 2 * tig;
        }

        float c[2][8][4];
#pragma unroll
        for (int m = 0; m < 2; m++)
#pragma unroll
            for (int n = 0; n < 8; n++)
#pragma unroll
                for (int j = 0; j < 4; j++) c[m][n][j] = 0.f;

        float2 pa[4][2];
#pragma unroll
        for (int j = 0; j < 4; j++) {
            pa[j][0] = *(const float2*)(Ap[j]);
            pa[j][1] = *(const float2*)(Ap[j] + 8);
        }

#pragma unroll 1
        for (int k = 0; k < 8; k++) {
            uint32_t ahA[4], alA[4], ahB[4], alB[4];
#pragma unroll
            for (int j = 0; j < 4; j++) {
                packsplit(pa[j][0], ahA[j], alA[j]);
                packsplit(pa[j][1], ahB[j], alB[j]);
            }
            if (k < 7) {
                int off = (k + 1) << 4;
#pragma unroll
                for (int j = 0; j < 4; j++) {
                    pa[j][0] = *(const float2*)(Ap[j] + off);
                    pa[j][1] = *(const float2*)(Ap[j] + off + 8);
                }
            }
            const uint32_t kb = smem_u32 + brow_off + colb + ((uint32_t)k << 5);
#pragma unroll
            for (int n2 = 0; n2 < 4; n2++) {
                uint32_t ha = kb + (uint32_t)(n2 * 16 * STRIDE * 2);
                uint32_t la = ha + BLO_ELEM * 2;
                uint32_t bh0, bh1, bh2, bh3, bl0, bl1, bl2, bl3;
                LDSM4(bh0, bh1, bh2, bh3, ha);
                LDSM4(bl0, bl1, bl2, bl3, la);
#pragma unroll
                for (int m = 0; m < 2; m++) {
                    uint32_t a0 = ahA[2 * m], a1 = ahA[2 * m + 1];
                    uint32_t a2 = ahB[2 * m], a3 = ahB[2 * m + 1];
                    uint32_t q0 = alA[2 * m], q1 = alA[2 * m + 1];
                    uint32_t q2 = alB[2 * m], q3 = alB[2 * m + 1];
                    mma16816(c[m][2 * n2], a0, a1, a2, a3, bh0, bh1);
                    mma16816(c[m][2 * n2], a0, a1, a2, a3, bl0, bl1);
                    mma16816(c[m][2 * n2], q0, q1, q2, q3, bh0, bh1);
                    mma16816(c[m][2 * n2 + 1], a0, a1, a2, a3, bh2, bh3);
                    mma16816(c[m][2 * n2 + 1], a0, a1, a2, a3, bl2, bl3);
                    mma16816(c[m][2 * n2 + 1], q0, q1, q2, q3, bh2, bh3);
                }
            }
        }

        // ---- epilogue ----
        int gc[4] = {0, 0, 0, 0};
        if (EPI == 0 || EPI == 2) {
#pragma unroll
            for (int j = 0; j < 4; j++)
                if (gv[j]) gc[j] = batch[grow[j]];
        }
#pragma unroll
        for (int m = 0; m < 2; m++) {
            int j0 = 2 * m, j1 = 2 * m + 1;
#pragma unroll
            for (int n = 0; n < 8; n++) {
                int col = wc * 64 + (n << 3) + 2 * tig;
                float2 bv = *(const float2*)(bias + col);
                float o0x = c[m][n][0] + bv.x, o0y = c[m][n][1] + bv.y;
                float o1x = c[m][n][2] + bv.x, o1y = c[m][n][3] + bv.y;
                if (EPI == 0) {
                    if (gv[j0]) {
                        float2 vv = *(const float2*)(vn + gc[j0] * Hh + col);
                        o0x += vv.x; o0y += vv.y;
                    }
                    if (gv[j1]) {
                        float2 vv = *(const float2*)(vn + gc[j1] * Hh + col);
                        o1x += vv.x; o1y += vv.y;
                    }
                } else {
                    o0x = fmaxf(o0x, 0.f); o0y = fmaxf(o0y, 0.f);
                    o1x = fmaxf(o1x, 0.f); o1y = fmaxf(o1y, 0.f);
                }
                if (gv[j0]) {
                    *(float2*)(C + (size_t)grow[j0] * Hh + col) = make_float2(o0x, o0y);
                    if (EPI == 2) {
                        atomicAdd(&pooled[gc[j0] * Hh + col], o0x);
                        atomicAdd(&pooled[gc[j0] * Hh + col + 1], o0y);
                    }
                }
                if (gv[j1]) {
                    *(float2*)(C + (size_t)grow[j1] * Hh + col) = make_float2(o1x, o1y);
                    if (EPI == 2) {
                        atomicAdd(&pooled[gc[j1] * Hh + col], o1x);
                        atomicAdd(&pooled[gc[j1] * Hh + col + 1], o1y);
                    }
                }
            }
        }
    }
}

// ======================= SpMM (unroll-4 edge loop) =======================
__launch_bounds__(256)
__global__ void spmm(const float* __restrict__ h, const float* __restrict__ eW,
                     const float* __restrict__ eb, float* __restrict__ agg) {
    __shared__ float sW[EDdim * Hh];
    for (int i = threadIdx.x; i < EDdim * Hh; i += 256) sW[i] = eW[i];
    __syncthreads();
    int warp = (blockIdx.x * 256 + threadIdx.x) >> 5;
    int lane = threadIdx.x & 31;
    if (warp >= NN) return;
    const int row = warp;
    const int c4 = lane << 2;

    float4 acc = make_float4(0.f, 0.f, 0.f, 0.f);
    const float* ea = g_eagg + row * EDdim;
#pragma unroll
    for (int k = 0; k < EDdim; k++) {
        float v = ea[k];
        float4 w = *(const float4*)&sW[k * Hh + c4];
        acc.x = fmaf(v, w.x, acc.x);
        acc.y = fmaf(v, w.y, acc.y);
        acc.z = fmaf(v, w.z, acc.z);
        acc.w = fmaf(v, w.w, acc.w);
    }
    int beg = g_rowptr[row];
    int end = g_rowptr[row + 1];
    float degf = (float)(end - beg);
    float4 bb = *(const float4*)(eb + c4);
    acc.x = fmaf(degf, bb.x, acc.x);
    acc.y = fmaf(degf, bb.y, acc.y);
    acc.z = fmaf(degf, bb.z, acc.z);
    acc.w = fmaf(degf, bb.w, acc.w);

    int e = beg;
    for (; e + 3 < end; e += 4) {
        int s0 = g_srcA[e];
        int s1 = g_srcA[e + 1];
        int s2 = g_srcA[e + 2];
        int s3 = g_srcA[e + 3];
        float4 h0 = *(const float4*)(h + (size_t)s0 * Hh + c4);
        float4 h1 = *(const float4*)(h + (size_t)s1 * Hh + c4);
        float4 h2 = *(const float4*)(h + (size_t)s2 * Hh + c4);
        float4 h3 = *(const float4*)(h + (size_t)s3 * Hh + c4);
        acc.x += (h0.x + h1.x) + (h2.x + h3.x);
        acc.y += (h0.y + h1.y) + (h2.y + h3.y);
        acc.z += (h0.z + h1.z) + (h2.z + h3.z);
        acc.w += (h0.w + h1.w) + (h2.w + h3.w);
    }
    for (; e < end; e++) {
        int s0 = g_srcA[e];
        float4 h0 = *(const float4*)(h + (size_t)s0 * Hh + c4);
        acc.x += h0.x;
        acc.y += h0.y;
        acc.z += h0.z;
        acc.w += h0.w;
    }
    *(float4*)(agg + (size_t)row * Hh + c4) = acc;
}

// ======================= small dense tails =======================
__global__ void vn_update(const float* __restrict__ w0, const float* __restrict__ b0,
                          const float* __restrict__ w1, const float* __restrict__ b1,
                          const float* __restrict__ pooled) {
    __shared__ float p[Hh];
    __shared__ float r0[Hh];
    int g = blockIdx.x, j = threadIdx.x;
    float cnt = fmaxf(g_z.counts[g], 1.f);
    p[j] = pooled[g * Hh + j] / cnt;
    __syncthreads();
    float s = b0[j];
    for (int k = 0; k < Hh; k++) s = fmaf(p[k], w0[k * Hh + j], s);
    r0[j] = fmaxf(s, 0.f);
    __syncthreads();
    float s2 = b1[j];
    for (int k = 0; k < Hh; k++) s2 = fmaf(r0[k], w1[k * Hh + j], s2);
    g_vn[g * Hh + j] += fmaxf(s2, 0.f);
}

__global__ void final_fc(const float* __restrict__ fcW, const float* __restrict__ fcb,
                         const float* __restrict__ pooled, float* __restrict__ out) {
    __shared__ float p[Hh];
    int g = blockIdx.x, j = threadIdx.x;
    float cnt = fmaxf(g_z.counts[g], 1.f);
    p[j] = pooled[g * Hh + j] / cnt;
    __syncthreads();
    float s = fcb[j];
    for (int k = 0; k < Hh; k++) s = fmaf(p[k], fcW[k * Hh + j], s);
    out[g * Hh + j] = s;
}

// ======================= launch =======================
extern "C" void kernel_launch(void* const* d_in, const int* in_sizes, int n_in,
                              void* d_out, int out_size) {
    const float* x      = (const float*)d_in[0];
    const float* eattr  = (const float*)d_in[1];
    const float* nodeW  = (const float*)d_in[2];
    const float* nodeB  = (const float*)d_in[3];
    const float* edgeW  = (const float*)d_in[4];
    const float* edgeB  = (const float*)d_in[5];
    const float* m1W    = (const float*)d_in[6];
    const float* m1B    = (const float*)d_in[7];
    const float* m2W    = (const float*)d_in[8];
    const float* m2B    = (const float*)d_in[9];
    const float* vnw0   = (const float*)d_in[10];
    const float* vnb0   = (const float*)d_in[11];
    const float* vnw1   = (const float*)d_in[12];
    const float* vnb1   = (const float*)d_in[13];
    const float* fcW    = (const float*)d_in[14];
    const float* fcB    = (const float*)d_in[15];
    const float* vninit = (const float*)d_in[16];
    const int*   eidx   = (const int*)d_in[17];
    const int*   batch  = (const int*)d_in[18];
    const int* srcp = eidx;
    const int* dstp = eidx + EE;
    float* out = (float*)d_out;

    void *p_z, *p_x, *p_h, *p_agg, *p_vn, *p_whi, *p_wlo;
    cudaGetSymbolAddress(&p_z, g_z);
    cudaGetSymbolAddress(&p_x, g_x);
    cudaGetSymbolAddress(&p_h, g_h);
    cudaGetSymbolAddress(&p_agg, g_agg);
    cudaGetSymbolAddress(&p_vn, g_vn);
    cudaGetSymbolAddress(&p_whi, g_whi);
    cudaGetSymbolAddress(&p_wlo, g_wlo);

    cudaFuncSetAttribute(gemm_tc<0>, cudaFuncAttributeMaxDynamicSharedMemorySize, GEMM_SMEM);
    cudaFuncSetAttribute(gemm_tc<1>, cudaFuncAttributeMaxDynamicSharedMemorySize, GEMM_SMEM);
    cudaFuncSetAttribute(gemm_tc<2>, cudaFuncAttributeMaxDynamicSharedMemorySize, GEMM_SMEM);

    const __nv_bfloat16* whi = (const __nv_bfloat16*)p_whi;
    const __nv_bfloat16* wlo = (const __nv_bfloat16*)p_wlo;
    // device pointer to pooled[l] inside g_z
    float* pooled0 = (float*)((char*)p_z + sizeof(int) * NN + sizeof(float) * Bb);

    // launches 1..5, persistent gemm0 at slot 6 for the ncu -s 5 -c 1 window
    cudaMemsetAsync(p_z, 0, sizeof(ZeroBlk));                 // 1  (deg+counts+pooled[5])
    k_wsplit<<<960, 256>>>(nodeW, m1W, m2W);                  // 2
    k_vn_init<<<Bb, Hh>>>(vninit);                            // 3
    k_counts<<<(NN + 255) / 256, 256>>>(batch);               // 4
    k_deg<<<(EE + 255) / 256, 256>>>(dstp);                   // 5
    gemm_tc<0><<<PGRID, 256, GEMM_SMEM>>>(x, whi, wlo, nodeB, // 6 <- profiled
                                          (float*)p_h, batch, (const float*)p_vn, nullptr, NN);

    // CSR build
    k_bsum<<<NBLK, 256>>>();
    k_bscanfill<<<NBLK, 256>>>();
    k_fill<<<(EE + 255) / 256, 256>>>(srcp, dstp);
    k_eagg<<<(NN + 7) / 8, 256>>>(eattr);

    const int SPB = (NN + 7) / 8;

    for (int l = 0; l < Ll; l++) {
        float* pooled_l = pooled0 + (size_t)l * Bb * Hh;
        if (l > 0) {
            gemm_tc<0><<<PGRID, 256, GEMM_SMEM>>>((const float*)p_x, whi + (size_t)l * Hh * Hh,
                                                  wlo + (size_t)l * Hh * Hh, nodeB + l * Hh,
                                                  (float*)p_h, batch, (const float*)p_vn, nullptr, NN);
        }
        spmm<<<SPB, 256>>>((const float*)p_h, edgeW + (size_t)l * EDdim * Hh,
                           edgeB + l * Hh, (float*)p_agg);
        gemm_tc<1><<<PGRID, 256, GEMM_SMEM>>>((const float*)p_agg, whi + (size_t)(5 + l) * Hh * Hh,
                                              wlo + (size_t)(5 + l) * Hh * Hh, m1B + l * Hh,
                                              (float*)p_h, nullptr, nullptr, nullptr, NN);
        gemm_tc<2><<<PGRID, 256, GEMM_SMEM>>>((const float*)p_h, whi + (size_t)(10 + l) * Hh * Hh,
                                              wlo + (size_t)(10 + l) * Hh * Hh, m2B + l * Hh,
                                              (float*)p_x, batch, nullptr, pooled_l, NN);
        if (l < Ll - 1) vn_update<<<Bb, Hh>>>(vnw0, vnb0, vnw1, vnb1, pooled_l);
    }
    final_fc<<<Bb, Hh>>>(fcW, fcB, pooled0 + (size_t)(Ll - 1) * Bb * Hh, out);
}